// round 6
// baseline (speedup 1.0000x reference)
#include <cuda_runtime.h>

// ConvCapsuleLayer: B=2, H=W=48, IN_CAPS=8, ATOMS=16, KER=3, OUT_CAPS=16, ROUTINGS=3
// Ho=Wo=46, N = 4232 positions. One CTA (128 threads) per position.
//
// Thread = (i = tid>>4, o = tid&15); lane = (i&1)*16 + o, so the softmax
// dimension o is 4 lane bits -> routing logits live in REGISTERS (l[k], one
// per kernel tap k) and softmax-over-o is a shfl_xor butterfly (masks 1,2,4,8).
// W[i,o] is register-resident for the whole kernel. Shared memory carries only:
// pose (warp-broadcast reads), act, the 4-warp s-partials, and v (stride-18
// rows => conflict-free float2 access).

#define HH 48
#define WW 48
#define CIN 136
#define HO 46
#define WO 46
#define NTH 128
#define ROUTINGS 3
#define VSTR 18   // v_s row stride: 18*o mod 32 distinct for o=0..15

#define DOT4(p, q) ((p).x*(q).x + (p).y*(q).y + (p).z*(q).z + (p).w*(q).w)

__global__ __launch_bounds__(NTH, 6)
void capsule_kernel(const float* __restrict__ x,
                    const float* __restrict__ Wg,
                    float* __restrict__ out)
{
    __shared__ __align__(16) float pose_s[72 * 16];   // [ki][a*4+b]
    __shared__ float act_s[72];
    __shared__ __align__(16) float spart[4][16 * 20]; // [warp][o*20 + e], padded
    __shared__ __align__(16) float v_s[16 * VSTR];    // [o][e], stride 18

    const int tid = threadIdx.x;
    const int n   = blockIdx.x;
    const int b   = n / (HO * WO);
    const int rem = n % (HO * WO);
    const int ho  = rem / WO;
    const int wo  = rem % WO;

    const int i_  = tid >> 4;   // 0..7
    const int o_  = tid & 15;   // 0..15
    const int wrp = tid >> 5;   // 0..3

    // ---- W[i_,o_] into registers (warp reads 2KB contiguous) ----
    const float4* wg = (const float4*)&Wg[tid * 16];
    const float4 w0 = wg[0], w1 = wg[1], w2 = wg[2], w3 = wg[3];

    // ---- load pose + act ----
    for (int idx = tid; idx < 72 * 17; idx += NTH) {
        int ki = idx / 17;
        int a  = idx - ki * 17;
        int k  = ki >> 3;
        int i  = ki & 7;
        int di = k / 3;
        int dj = k - di * 3;
        float val = x[(size_t)(((b * HH + ho + di) * WW) + (wo + dj)) * CIN + i * 17 + a];
        if (a < 16) pose_s[ki * 16 + a] = val;
        else        act_s[ki] = val;
    }
    __syncthreads();

    // ---- act[k*8+i_] into registers (9 broadcast-ish scalar LDS, once) ----
    float actk[9];
    #pragma unroll
    for (int k = 0; k < 9; k++) actk[k] = act_s[k * 8 + i_];

    // ---- routing logits in registers: l[k] = logits[k*8+i_][o_] ----
    float l[9];
    #pragma unroll
    for (int k = 0; k < 9; k++) l[k] = 0.0f;

    #pragma unroll 1
    for (int r = 0; r < ROUTINGS; r++) {
        // ---- A: coup_k = softmax_o(l)*act (shfl butterfly over the o bits) ----
        float coupk[9];
        if (r == 0) {
            #pragma unroll
            for (int k = 0; k < 9; k++) coupk[k] = actk[k] * 0.0625f;  // softmax(0)=1/16
        } else {
            #pragma unroll
            for (int k = 0; k < 9; k++) {
                float m = l[k];
                m = fmaxf(m, __shfl_xor_sync(0xffffffffu, m, 1));
                m = fmaxf(m, __shfl_xor_sync(0xffffffffu, m, 2));
                m = fmaxf(m, __shfl_xor_sync(0xffffffffu, m, 4));
                m = fmaxf(m, __shfl_xor_sync(0xffffffffu, m, 8));
                float e = __expf(l[k] - m);
                float s = e;
                s += __shfl_xor_sync(0xffffffffu, s, 1);
                s += __shfl_xor_sync(0xffffffffu, s, 2);
                s += __shfl_xor_sync(0xffffffffu, s, 4);
                s += __shfl_xor_sync(0xffffffffu, s, 8);
                coupk[k] = e * (actk[k] / s);
            }
        }

        // ---- B: P[e] = sum_k coupk[k] * pose[k*8+i_][e] (registers) ----
        float4 P0 = make_float4(0.f,0.f,0.f,0.f);
        float4 P1 = make_float4(0.f,0.f,0.f,0.f);
        float4 P2 = make_float4(0.f,0.f,0.f,0.f);
        float4 P3 = make_float4(0.f,0.f,0.f,0.f);
        #pragma unroll
        for (int k = 0; k < 9; k++) {
            const float c = coupk[k];
            const float4* pr = (const float4*)&pose_s[(k * 8 + i_) * 16];  // 2-addr bcast
            float4 p0 = pr[0], p1 = pr[1], p2 = pr[2], p3 = pr[3];
            P0.x += c*p0.x; P0.y += c*p0.y; P0.z += c*p0.z; P0.w += c*p0.w;
            P1.x += c*p1.x; P1.y += c*p1.y; P1.z += c*p1.z; P1.w += c*p1.w;
            P2.x += c*p2.x; P2.y += c*p2.y; P2.z += c*p2.z; P2.w += c*p2.w;
            P3.x += c*p3.x; P3.y += c*p3.y; P3.z += c*p3.z; P3.w += c*p3.w;
        }

        // ---- C: M = P @ W (regs); pair-reduce i via shfl(16); 4-warp partials ----
        {
            float4 M0, M1, M2, M3;
            M0.x = P0.x*w0.x + P0.y*w1.x + P0.z*w2.x + P0.w*w3.x;
            M0.y = P0.x*w0.y + P0.y*w1.y + P0.z*w2.y + P0.w*w3.y;
            M0.z = P0.x*w0.z + P0.y*w1.z + P0.z*w2.z + P0.w*w3.z;
            M0.w = P0.x*w0.w + P0.y*w1.w + P0.z*w2.w + P0.w*w3.w;
            M1.x = P1.x*w0.x + P1.y*w1.x + P1.z*w2.x + P1.w*w3.x;
            M1.y = P1.x*w0.y + P1.y*w1.y + P1.z*w2.y + P1.w*w3.y;
            M1.z = P1.x*w0.z + P1.y*w1.z + P1.z*w2.z + P1.w*w3.z;
            M1.w = P1.x*w0.w + P1.y*w1.w + P1.z*w2.w + P1.w*w3.w;
            M2.x = P2.x*w0.x + P2.y*w1.x + P2.z*w2.x + P2.w*w3.x;
            M2.y = P2.x*w0.y + P2.y*w1.y + P2.z*w2.y + P2.w*w3.y;
            M2.z = P2.x*w0.z + P2.y*w1.z + P2.z*w2.z + P2.w*w3.z;
            M2.w = P2.x*w0.w + P2.y*w1.w + P2.z*w2.w + P2.w*w3.w;
            M3.x = P3.x*w0.x + P3.y*w1.x + P3.z*w2.x + P3.w*w3.x;
            M3.y = P3.x*w0.y + P3.y*w1.y + P3.z*w2.y + P3.w*w3.y;
            M3.z = P3.x*w0.z + P3.y*w1.z + P3.z*w2.z + P3.w*w3.z;
            M3.w = P3.x*w0.w + P3.y*w1.w + P3.z*w2.w + P3.w*w3.w;

            #define XR(f) f += __shfl_xor_sync(0xffffffffu, f, 16)
            XR(M0.x); XR(M0.y); XR(M0.z); XR(M0.w);
            XR(M1.x); XR(M1.y); XR(M1.z); XR(M1.w);
            XR(M2.x); XR(M2.y); XR(M2.z); XR(M2.w);
            XR(M3.x); XR(M3.y); XR(M3.z); XR(M3.w);
            #undef XR

            float4* dst = (float4*)&spart[wrp][o_ * 20];
            if ((tid & 16) == 0) { dst[0] = M0; dst[1] = M1; }
            else                 { dst[2] = M2; dst[3] = M3; }
        }
        __syncthreads();

        // ---- D: s = sum_w spart; squash; write v (stride-18) or out ----
        {
            const int o = tid >> 3, g = tid & 7;
            const int off = o * 20 + g * 2;
            float2 a0 = *(const float2*)&spart[0][off];
            float2 a1 = *(const float2*)&spart[1][off];
            float2 a2 = *(const float2*)&spart[2][off];
            float2 a3 = *(const float2*)&spart[3][off];
            float2 sv = make_float2(a0.x + a1.x + a2.x + a3.x,
                                    a0.y + a1.y + a2.y + a3.y);
            float part = sv.x * sv.x + sv.y * sv.y;
            part += __shfl_xor_sync(0xffffffffu, part, 1);
            part += __shfl_xor_sync(0xffffffffu, part, 2);
            part += __shfl_xor_sync(0xffffffffu, part, 4);
            const float sq = part;
            const float scale = (sq / (1.0f + sq)) * rsqrtf(sq + 1e-7f);
            float2 vv = make_float2(sv.x * scale, sv.y * scale);
            if (r == ROUTINGS - 1) {
                *(float2*)&out[(size_t)n * 256 + tid * 2] = vv;
            } else {
                *(float2*)&v_s[o * VSTR + g * 2] = vv;
            }
        }
        if (r == ROUTINGS - 1) break;
        __syncthreads();

        // ---- E+F fused: Q = f(v[o_], Wreg); l[k] += dot16(pose[k*8+i_], Q) ----
        {
            float2 va = *(const float2*)&v_s[o_ * VSTR +  0];
            float2 vb = *(const float2*)&v_s[o_ * VSTR +  2];
            float2 vc = *(const float2*)&v_s[o_ * VSTR +  4];
            float2 vd = *(const float2*)&v_s[o_ * VSTR +  6];
            float2 ve = *(const float2*)&v_s[o_ * VSTR +  8];
            float2 vf = *(const float2*)&v_s[o_ * VSTR + 10];
            float2 vg = *(const float2*)&v_s[o_ * VSTR + 12];
            float2 vh = *(const float2*)&v_s[o_ * VSTR + 14];
            float4 v0 = make_float4(va.x, va.y, vb.x, vb.y);
            float4 v1 = make_float4(vc.x, vc.y, vd.x, vd.y);
            float4 v2 = make_float4(ve.x, ve.y, vf.x, vf.y);
            float4 v3 = make_float4(vg.x, vg.y, vh.x, vh.y);

            float4 Q0, Q1, Q2, Q3;   // Qa.{x..w} = Q[a][b]
            Q0.x = DOT4(v0,w0); Q0.y = DOT4(v0,w1); Q0.z = DOT4(v0,w2); Q0.w = DOT4(v0,w3);
            Q1.x = DOT4(v1,w0); Q1.y = DOT4(v1,w1); Q1.z = DOT4(v1,w2); Q1.w = DOT4(v1,w3);
            Q2.x = DOT4(v2,w0); Q2.y = DOT4(v2,w1); Q2.z = DOT4(v2,w2); Q2.w = DOT4(v2,w3);
            Q3.x = DOT4(v3,w0); Q3.y = DOT4(v3,w1); Q3.z = DOT4(v3,w2); Q3.w = DOT4(v3,w3);
            #pragma unroll
            for (int k = 0; k < 9; k++) {
                const float4* pr = (const float4*)&pose_s[(k * 8 + i_) * 16];  // bcast
                float4 p0 = pr[0], p1 = pr[1], p2 = pr[2], p3 = pr[3];
                l[k] += DOT4(p0, Q0) + DOT4(p1, Q1) + DOT4(p2, Q2) + DOT4(p3, Q3);
            }
        }
        __syncthreads();
    }
}

extern "C" void kernel_launch(void* const* d_in, const int* in_sizes, int n_in,
                              void* d_out, int out_size)
{
    const float* x = (const float*)d_in[0];
    const float* W = (const float*)d_in[1];
    if (n_in >= 2 && in_sizes[0] == 2048) {   // defensive: W has 2048 elems
        const float* t = x; x = W; W = t;
    }
    float* out = (float*)d_out;
    capsule_kernel<<<2 * HO * WO, NTH>>>(x, W, out);
}